// round 12
// baseline (speedup 1.0000x reference)
#include <cuda_runtime.h>
#include <cuda_fp16.h>
#include <math.h>
#include <stdint.h>

// ---------------------------------------------------------------------------
// MoEImage via fp16 mma.sync m16n8k16 (fp32 accumulate).
//   wquant : round 11 64x64 weight matrices to fp16 ([o][k] layout)
//   feat   : F = gelu(x@W^T+b); d_feat stored [b][pix][c] fp16; fused gf sums
//   gate   : reduce gf partials (transposed, coalesced) -> MLP -> top2 -> d_dw
//   out    : 4-matrix fp16 GEMM; warp = (o-quarter, mat-pair), register
//            combine per pair, 2-buffer smem combine across pairs
// R12: swzb now XORs (row^(row>>3))&7 (kills 16-way conflict in feat x-staging);
//      feat_kernel gets __launch_bounds__(256,2) (was unbounded regs -> 1 CTA/SM).
// ---------------------------------------------------------------------------

#define NPIX   16384
#define NPIX_B (64 * 16384)

__device__ __align__(16) __half d_feat[32 * 64 * 16384];   // [b][pix][c], 64 MiB
__device__ float d_gf_part[64 * 4096];                     // [c][block]
__device__ float d_dw[32 * 8];
__device__ __align__(16) __half d_wq[11 * 4096];           // 0: fe, 1-2: shared, 3-10: experts

__device__ __forceinline__ float gelu_f(float v) {
    return 0.5f * v * (1.0f + erff(v * 0.70710678118654752440f));
}
// half tiles: rows of 64 halves = 128B = 8 segs of 16B; byte offset
__device__ __forceinline__ int swzb(int row, int seg) {
    return row * 128 + ((seg ^ ((row ^ (row >> 3)) & 7)) << 4);
}
// f32 tiles: rows of 64 floats = 16 segs of 16B; float offset
__device__ __forceinline__ int swz(int row, int seg) {
    return (row << 6) + ((seg ^ ((row ^ (row >> 3)) & 7)) << 2);
}
__device__ __forceinline__ void ldsm4(uint32_t a, uint32_t& r0, uint32_t& r1,
                                      uint32_t& r2, uint32_t& r3) {
    asm volatile("ldmatrix.sync.aligned.m8n8.x4.shared.b16 {%0,%1,%2,%3}, [%4];"
                 : "=r"(r0), "=r"(r1), "=r"(r2), "=r"(r3) : "r"(a));
}
__device__ __forceinline__ void mma16(float& c0, float& c1, float& c2, float& c3,
                                      uint32_t a0, uint32_t a1, uint32_t a2, uint32_t a3,
                                      uint32_t b0, uint32_t b1) {
    asm volatile("mma.sync.aligned.m16n8k16.row.col.f32.f16.f16.f32 "
                 "{%0,%1,%2,%3},{%4,%5,%6,%7},{%8,%9},{%0,%1,%2,%3};"
                 : "+f"(c0), "+f"(c1), "+f"(c2), "+f"(c3)
                 : "r"(a0), "r"(a1), "r"(a2), "r"(a3), "r"(b0), "r"(b1));
}
__device__ __forceinline__ uint32_t h2u(__half2 h) {
    return *reinterpret_cast<uint32_t*>(&h);
}

// --------------------------- weight quantize -------------------------------
__global__ __launch_bounds__(256) void wquant_kernel(
    const float* __restrict__ fe_w, const float* __restrict__ s_w,
    const float* __restrict__ e_w)
{
    const int m = blockIdx.x;   // 0..10
    const float* src = (m == 0) ? fe_w
                     : (m <= 2) ? s_w + (m - 1) * 4096
                                : e_w + (m - 3) * 4096;
    __half* dst = d_wq + m * 4096;
    for (int i = threadIdx.x; i < 4096; i += 256) dst[i] = __float2half_rn(src[i]);
}

// ------------------------------ Phase A ------------------------------------
// grid = 32 b * 128 tiles of 128 pix; block 256 = 8 warps.
// GEMM: m = pix (8 strips of 16), n = o (8 tiles), k = c (4 steps of 16).
__global__ void __launch_bounds__(256, 2) feat_kernel(
    const float* __restrict__ x, const float* __restrict__ fe_b)
{
    extern __shared__ __align__(16) char smem[];
    // [0, 16KB)  sxT [128 pix][64 c] half swz; reused as sc [128 pix][64 o]
    // [16KB, 24KB) swt [64 o][64 k] half swz
    const uint32_t smem_sh = (uint32_t)__cvta_generic_to_shared(smem);
    __shared__ float sb[64];
    __shared__ float red[8 * 64];

    const int tid = threadIdx.x, w = tid >> 5, l = tid & 31;
    const int b = blockIdx.x >> 7, pix0 = (blockIdx.x & 127) << 7;

    // stage fe weights (fp16, pre-rounded)
#pragma unroll
    for (int r = 0; r < 2; r++) {
        int i4 = tid + r * 256;
        uint4 v = *(const uint4*)((const char*)d_wq + i4 * 16);
        *(uint4*)(smem + 16384 + swzb(i4 >> 3, i4 & 7)) = v;
    }
    if (tid < 64) sb[tid] = fe_b[tid];

    // stage x^T [pix][c] as fp16: warp w = channel octet, lane covers 4 pix
    {
        const float* xb = x + (size_t)b * NPIX_B + pix0;
        float4 v[8];
#pragma unroll
        for (int j = 0; j < 8; j++)
            v[j] = *(const float4*)(xb + (size_t)(8 * w + j) * NPIX + 4 * l);
#pragma unroll
        for (int p = 0; p < 4; p++) {
            uint4 u;
            u.x = h2u(__floats2half2_rn(((float*)&v[0])[p], ((float*)&v[1])[p]));
            u.y = h2u(__floats2half2_rn(((float*)&v[2])[p], ((float*)&v[3])[p]));
            u.z = h2u(__floats2half2_rn(((float*)&v[4])[p], ((float*)&v[5])[p]));
            u.w = h2u(__floats2half2_rn(((float*)&v[6])[p], ((float*)&v[7])[p]));
            *(uint4*)(smem + swzb(4 * l + p, w)) = u;
        }
    }
    __syncthreads();

    float acc[8][4];
    const int c0p = 2 * (l & 3);
#pragma unroll
    for (int nt = 0; nt < 8; nt++) {
        float b0v = sb[nt * 8 + c0p], b1v = sb[nt * 8 + c0p + 1];
        acc[nt][0] = b0v; acc[nt][1] = b1v;
        acc[nt][2] = b0v; acc[nt][3] = b1v;
    }

    const int tq = l >> 3, r8 = l & 7;
#pragma unroll
    for (int kk = 0; kk < 4; kk++) {
        const int aseg = 2 * kk + (tq >> 1);
        const int rsub = (tq & 1) * 8 + r8;
        uint32_t a0, a1, a2, a3;
        ldsm4(smem_sh + swzb(16 * w + rsub, aseg), a0, a1, a2, a3);
        uint32_t Bf[8][2];
#pragma unroll
        for (int g = 0; g < 4; g++) {
            uint32_t r0, r1, r2, r3;
            ldsm4(smem_sh + 16384 + swzb(16 * g + rsub, aseg), r0, r1, r2, r3);
            Bf[2 * g][0] = r0;     Bf[2 * g][1] = r2;
            Bf[2 * g + 1][0] = r1; Bf[2 * g + 1][1] = r3;
        }
#pragma unroll
        for (int nt = 0; nt < 8; nt++)
            mma16(acc[nt][0], acc[nt][1], acc[nt][2], acc[nt][3],
                  a0, a1, a2, a3, Bf[nt][0], Bf[nt][1]);
    }

    // gelu in fp32
#pragma unroll
    for (int nt = 0; nt < 8; nt++)
#pragma unroll
        for (int i = 0; i < 4; i++) acc[nt][i] = gelu_f(acc[nt][i]);

    // per-channel partial sums (fp32, before fp16 rounding)
#pragma unroll
    for (int nt = 0; nt < 8; nt++) {
        float p0 = acc[nt][0] + acc[nt][2];
        float p1 = acc[nt][1] + acc[nt][3];
#pragma unroll
        for (int mk = 4; mk <= 16; mk <<= 1) {
            p0 += __shfl_xor_sync(0xffffffffu, p0, mk);
            p1 += __shfl_xor_sync(0xffffffffu, p1, mk);
        }
        if (l < 4) {
            red[w * 64 + nt * 8 + 2 * l]     = p0;
            red[w * 64 + nt * 8 + 2 * l + 1] = p1;
        }
    }

    __syncthreads();   // sxT/swt reads done -> reuse sxT region as sc
    {
        const int pr = 16 * w + (l >> 2);
#pragma unroll
        for (int nt = 0; nt < 8; nt++) {
            __half2 lo = __floats2half2_rn(acc[nt][0], acc[nt][1]);
            __half2 hi = __floats2half2_rn(acc[nt][2], acc[nt][3]);
            *(__half2*)(smem + swzb(pr, nt) + c0p * 2) = lo;
            *(__half2*)(smem + swzb(pr + 8, nt) + c0p * 2) = hi;
        }
    }
    __syncthreads();

    // copy-out [pix][c] fp16
    char* fb = (char*)(d_feat + ((size_t)b * NPIX + pix0) * 64);
#pragma unroll
    for (int r = 0; r < 4; r++) {
        int i4 = tid + r * 256;
        uint4 v = *(uint4*)(smem + swzb(i4 >> 3, i4 & 7));
        *(uint4*)(fb + i4 * 16) = v;
    }
    if (tid < 64) {
        float s = 0.f;
#pragma unroll
        for (int ww = 0; ww < 8; ww++) s += red[ww * 64 + tid];
        d_gf_part[tid * 4096 + blockIdx.x] = s;
    }
}

// ------------------------------ Phase C ------------------------------------
__global__ __launch_bounds__(256) void gate_kernel(
    const float* __restrict__ g1_w, const float* __restrict__ g1_b,
    const float* __restrict__ bn1_g, const float* __restrict__ bn1_b,
    const float* __restrict__ ca1_w, const float* __restrict__ ca1_b,
    const float* __restrict__ ca2_w, const float* __restrict__ ca2_b,
    const float* __restrict__ g2_w, const float* __restrict__ g2_b,
    const float* __restrict__ bn2_g, const float* __restrict__ bn2_b,
    const float* __restrict__ g3_w, const float* __restrict__ g3_b)
{
    __shared__ float sgf[32 * 64];
    __shared__ float sh1[32 * 128];
    __shared__ float sm[32 * 8];
    __shared__ float shh[32 * 64];
    __shared__ float ssc[32 * 8];
    const int tid = threadIdx.x;
    const float rs = rsqrtf(1.0f + 1e-5f);

    for (int i = tid; i < 2048; i += 256) {
        int bb = i >> 6, c = i & 63;
        const float4* pp = (const float4*)(d_gf_part + c * 4096 + bb * 128);
        float s = 0.f;
#pragma unroll 8
        for (int j = 0; j < 32; j++) {
            float4 v = pp[j];
            s += (v.x + v.y) + (v.z + v.w);
        }
        sgf[i] = s * (1.0f / 16384.0f);
    }
    __syncthreads();

    for (int i = tid; i < 32 * 128; i += 256) {
        int b = i >> 7, j = i & 127;
        float a = g1_b[j];
        const float* gr = sgf + b * 64;
        const float* wr = g1_w + j * 64;
#pragma unroll 8
        for (int c = 0; c < 64; c++) a = fmaf(gr[c], wr[c], a);
        a = a * (bn1_g[j] * rs) + bn1_b[j];
        sh1[i] = gelu_f(a);
    }
    __syncthreads();

    {
        int b = tid >> 3, k = tid & 7;
        float a = ca1_b[k];
        const float* hr = sh1 + b * 128;
        const float* wr = ca1_w + k * 128;
#pragma unroll 8
        for (int j = 0; j < 128; j++) a = fmaf(hr[j], wr[j], a);
        sm[tid] = gelu_f(a);
    }
    __syncthreads();

    for (int i = tid; i < 32 * 128; i += 256) {
        int b = i >> 7, j = i & 127;
        float a = ca2_b[j];
        const float* mr = sm + b * 8;
        const float* wr = ca2_w + j * 8;
#pragma unroll
        for (int k = 0; k < 8; k++) a = fmaf(mr[k], wr[k], a);
        sh1[i] *= 1.0f / (1.0f + expf(-2.0f * a));
    }
    __syncthreads();

    for (int i = tid; i < 32 * 64; i += 256) {
        int b = i >> 6, o = i & 63;
        float a = g2_b[o];
        const float* hr = sh1 + b * 128;
        const float* wr = g2_w + o * 128;
#pragma unroll 8
        for (int j = 0; j < 128; j++) a = fmaf(hr[j], wr[j], a);
        a = a * (bn2_g[o] * rs) + bn2_b[o];
        shh[i] = gelu_f(a);
    }
    __syncthreads();

    {
        int b = tid >> 3, e = tid & 7;
        float a = g3_b[e];
        const float* hr = shh + b * 64;
        const float* wr = g3_w + e * 64;
#pragma unroll 8
        for (int c = 0; c < 64; c++) a = fmaf(hr[c], wr[c], a);
        ssc[tid] = a;
    }
    __syncthreads();

    if (tid < 32) {
        const float* sc = ssc + tid * 8;
        int i1 = 0; float v1 = sc[0];
#pragma unroll
        for (int e = 1; e < 8; e++) if (sc[e] > v1) { v1 = sc[e]; i1 = e; }
        int i2 = -1; float v2 = -3.4e38f;
#pragma unroll
        for (int e = 0; e < 8; e++) if (e != i1 && sc[e] > v2) { v2 = sc[e]; i2 = e; }
        float w1 = 1.0f / (1.0f + expf((v2 - v1) * 0.5f));
        float* dw = d_dw + tid * 8;
#pragma unroll
        for (int e = 0; e < 8; e++) dw[e] = 0.0f;
        dw[i1] = w1;
        dw[i2] = 1.0f - w1;
    }
}

// ------------------------------ Phase D ------------------------------------
// grid = 32 b * 256 tiles of 64 pix; block 256 = 8 warps.
// warp: q = w&3 -> o rows [16q,16q+16); g = w>>2 -> mats {2g, 2g+1}.
// A = weights [o][k] fp16, B = features [pix][k] fp16; B frags shared by pair.
__global__ void __launch_bounds__(256, 2) out_kernel(
    const float* __restrict__ s_b, const float* __restrict__ e_b,
    float* __restrict__ out)
{
    extern __shared__ __align__(16) char smem[];
    // [0, 8KB)     sfB [64 pix][64 k] half swz
    // [8KB, 40KB)  sw4 [4 mat][64 o][64 k] half swz; reused: buf[2][64][64] f32
    const uint32_t smem_sh = (uint32_t)__cvta_generic_to_shared(smem);
    __shared__ float Bv[256];
    __shared__ float cws[4];
    __shared__ int msel[4];

    const int tid = threadIdx.x, w = tid >> 5, l = tid & 31;
    const int b = blockIdx.x >> 8, pix0 = (blockIdx.x & 255) << 6;

    if (tid == 0) {
        int s0 = -1, s1 = -1; float w0 = 0.f, w1 = 0.f;
        const float* dw = d_dw + b * 8;
#pragma unroll
        for (int e = 0; e < 8; e++) {
            float v = dw[e];
            if (v != 0.0f) { if (s0 < 0) { s0 = e; w0 = v; } else { s1 = e; w1 = v; } }
        }
        msel[0] = 1; msel[1] = 2; msel[2] = 3 + s0; msel[3] = 3 + s1;
        cws[0] = 0.5f; cws[1] = 0.5f; cws[2] = w0; cws[3] = w1;
    }
    __syncthreads();

    // stage 4 weight matrices (fp16, swizzled): 2048 uint4
#pragma unroll
    for (int r = 0; r < 8; r++) {
        int idx = tid + r * 256;
        int m = idx >> 9, i4 = idx & 511;
        uint4 v = *(const uint4*)((const char*)d_wq + msel[m] * 8192 + i4 * 16);
        *(uint4*)(smem + 8192 + m * 8192 + swzb(i4 >> 3, i4 & 7)) = v;
    }
    // stage features [pix][k] (contiguous fp16 rows): 512 uint4
    {
        const char* fb = (const char*)(d_feat + ((size_t)b * NPIX + pix0) * 64);
#pragma unroll
        for (int r = 0; r < 2; r++) {
            int i4 = tid + r * 256;
            uint4 v = *(const uint4*)(fb + i4 * 16);
            *(uint4*)(smem + swzb(i4 >> 3, i4 & 7)) = v;
        }
    }
    if (tid < 64) {
        Bv[tid]       = s_b[tid];
        Bv[64 + tid]  = s_b[64 + tid];
        Bv[128 + tid] = e_b[(msel[2] - 3) * 64 + tid];
        Bv[192 + tid] = e_b[(msel[3] - 3) * 64 + tid];
    }
    __syncthreads();

    const int q = w & 3, g = w >> 2;
    const int ma = 2 * g, mb = 2 * g + 1;
    const uint32_t swa = smem_sh + 8192 + ma * 8192;
    const uint32_t swb = smem_sh + 8192 + mb * 8192;

    const int ro = 16 * q + (l >> 2), c0p = 2 * (l & 3);
    float accA[8][4], accB[8][4];
#pragma unroll
    for (int nt = 0; nt < 8; nt++) {
        float a0v = Bv[ma * 64 + ro], a1v = Bv[ma * 64 + ro + 8];
        float b0v = Bv[mb * 64 + ro], b1v = Bv[mb * 64 + ro + 8];
        accA[nt][0] = a0v; accA[nt][1] = a0v; accA[nt][2] = a1v; accA[nt][3] = a1v;
        accB[nt][0] = b0v; accB[nt][1] = b0v; accB[nt][2] = b1v; accB[nt][3] = b1v;
    }

    const int tq = l >> 3, r8 = l & 7;
#pragma unroll
    for (int kk = 0; kk < 4; kk++) {
        const int aseg = 2 * kk + (tq >> 1);
        const int rsub = (tq & 1) * 8 + r8;
        uint32_t Bf[8][2];
#pragma unroll
        for (int g2 = 0; g2 < 4; g2++) {
            uint32_t r0, r1, r2, r3;
            ldsm4(smem_sh + swzb(16 * g2 + rsub, aseg), r0, r1, r2, r3);
            Bf[2 * g2][0] = r0;     Bf[2 * g2][1] = r2;
            Bf[2 * g2 + 1][0] = r1; Bf[2 * g2 + 1][1] = r3;
        }
        uint32_t a0, a1, a2, a3;
        ldsm4(swa + swzb(16 * q + rsub, aseg), a0, a1, a2, a3);
#pragma unroll
        for (int nt = 0; nt < 8; nt++)
            mma16(accA[nt][0], accA[nt][1], accA[nt][2], accA[nt][3],
                  a0, a1, a2, a3, Bf[nt][0], Bf[nt][1]);
        ldsm4(swb + swzb(16 * q + rsub, aseg), a0, a1, a2, a3);
#pragma unroll
        for (int nt = 0; nt < 8; nt++)
            mma16(accB[nt][0], accB[nt][1], accB[nt][2], accB[nt][3],
                  a0, a1, a2, a3, Bf[nt][0], Bf[nt][1]);
    }

    const float ca = cws[ma], cb = cws[mb];
    __syncthreads();   // weights dead -> reuse as 2 combine buffers [g][o][pix] f32
    {
        float* buf = (float*)(smem + 8192) + g * 4096;
#pragma unroll
        for (int nt = 0; nt < 8; nt++) {
            int pix = nt * 8 + c0p;
            float v0 = ca * gelu_f(accA[nt][0]) + cb * gelu_f(accB[nt][0]);
            float v1 = ca * gelu_f(accA[nt][1]) + cb * gelu_f(accB[nt][1]);
            float v2 = ca * gelu_f(accA[nt][2]) + cb * gelu_f(accB[nt][2]);
            float v3 = ca * gelu_f(accA[nt][3]) + cb * gelu_f(accB[nt][3]);
            *(float2*)(buf + swz(ro, pix >> 2) + (pix & 3))     = make_float2(v0, v1);
            *(float2*)(buf + swz(ro + 8, pix >> 2) + (pix & 3)) = make_float2(v2, v3);
        }
    }
    __syncthreads();

    float* ob = out + (size_t)b * NPIX_B + pix0;
    const float* b0p = (const float*)(smem + 8192);
    const float* b1p = b0p + 4096;
#pragma unroll
    for (int r = 0; r < 4; r++) {
        int i4 = tid + r * 256;
        int o = i4 >> 4, seg = i4 & 15;
        int off = swz(o, seg);
        float4 va = *(const float4*)(b0p + off);
        float4 vb = *(const float4*)(b1p + off);
        float4 rr;
        rr.x = va.x + vb.x; rr.y = va.y + vb.y;
        rr.z = va.z + vb.z; rr.w = va.w + vb.w;
        *(float4*)(ob + (size_t)o * NPIX + seg * 4) = rr;
    }
}

// ---------------------------------------------------------------------------
extern "C" void kernel_launch(void* const* d_in, const int* in_sizes, int n_in,
                              void* d_out, int out_size)
{
    const float* x     = (const float*)d_in[0];
    const float* fe_w  = (const float*)d_in[1];
    const float* fe_b  = (const float*)d_in[2];
    const float* s_w   = (const float*)d_in[3];
    const float* s_b   = (const float*)d_in[4];
    const float* e_w   = (const float*)d_in[5];
    const float* e_b   = (const float*)d_in[6];
    const float* g1_w  = (const float*)d_in[7];
    const float* g1_b  = (const float*)d_in[8];
    const float* bn1_g = (const float*)d_in[9];
    const float* bn1_b = (const float*)d_in[10];
    const float* ca1_w = (const float*)d_in[11];
    const float* ca1_b = (const float*)d_in[12];
    const float* ca2_w = (const float*)d_in[13];
    const float* ca2_b = (const float*)d_in[14];
    const float* g2_w  = (const float*)d_in[15];
    const float* g2_b  = (const float*)d_in[16];
    const float* bn2_g = (const float*)d_in[17];
    const float* bn2_b = (const float*)d_in[18];
    const float* g3_w  = (const float*)d_in[19];
    const float* g3_b  = (const float*)d_in[20];
    float* out = (float*)d_out;

    wquant_kernel<<<11, 256>>>(fe_w, s_w, e_w);
    feat_kernel<<<4096, 256, 24576>>>(x, fe_b);
    gate_kernel<<<1, 256>>>(g1_w, g1_b, bn1_g, bn1_b, ca1_w, ca1_b,
                            ca2_w, ca2_b, g2_w, g2_b, bn2_g, bn2_b,
                            g3_w, g3_b);
    out_kernel<<<8192, 256, 40960>>>(s_b, e_b, out);
}

// round 16
// speedup vs baseline: 1.0744x; 1.0744x over previous
#include <cuda_runtime.h>
#include <cuda_fp16.h>
#include <math.h>
#include <stdint.h>

// ---------------------------------------------------------------------------
// MoEImage via fp16 mma.sync m16n8k16 (fp32 accumulate).
//   wquant : round 11 64x64 weight matrices to fp16 ([o][k] layout)
//   feat   : F = gelu(x@W^T+b); d_feat stored [b][pix][c] fp16; fused gf sums
//   gate   : reduce gf partials -> MLP -> top2 -> d_dw
//   out    : persistent 4-tile blocks, resident weights, cp.async
//            double-buffered feature tiles, fast MUFU gelu epilogue
// ---------------------------------------------------------------------------

#define NPIX   16384
#define NPIX_B (64 * 16384)

__device__ __align__(16) __half d_feat[32 * 64 * 16384];   // [b][pix][c], 64 MiB
__device__ float d_gf_part[64 * 4096];                     // [c][block]
__device__ float d_dw[32 * 8];
__device__ __align__(16) __half d_wq[11 * 4096];           // 0: fe, 1-2: shared, 3-10: experts

// Branchless erf-based gelu (A&S 7.1.26, abs err ~1.5e-7) using MUFU rcp/ex2.
__device__ __forceinline__ float gelu_f(float v) {
    float u = fabsf(v) * 0.70710678118654752440f;
    float d;
    asm("rcp.approx.f32 %0, %1;" : "=f"(d) : "f"(fmaf(0.3275911f, u, 1.0f)));
    float p = fmaf(d, 1.061405429f, -1.453152027f);
    p = fmaf(d, p, 1.421413741f);
    p = fmaf(d, p, -0.284496736f);
    p = fmaf(d, p, 0.254829592f);
    p = p * d;
    float e;
    asm("ex2.approx.f32 %0, %1;" : "=f"(e)
        : "f"(u * u * -1.4426950408889634f));
    float erfu = fmaf(-p, e, 1.0f);          // erf(u), u >= 0
    float s = copysignf(erfu, v);
    float hv = 0.5f * v;
    return fmaf(hv, s, hv);
}
// half tiles: rows of 64 halves = 128B = 8 segs of 16B; byte offset
__device__ __forceinline__ int swzb(int row, int seg) {
    return row * 128 + ((seg ^ ((row ^ (row >> 3)) & 7)) << 4);
}
// f32 tiles: rows of 64 floats = 16 segs of 16B; float offset
__device__ __forceinline__ int swz(int row, int seg) {
    return (row << 6) + ((seg ^ ((row ^ (row >> 3)) & 7)) << 2);
}
__device__ __forceinline__ void ldsm4(uint32_t a, uint32_t& r0, uint32_t& r1,
                                      uint32_t& r2, uint32_t& r3) {
    asm volatile("ldmatrix.sync.aligned.m8n8.x4.shared.b16 {%0,%1,%2,%3}, [%4];"
                 : "=r"(r0), "=r"(r1), "=r"(r2), "=r"(r3) : "r"(a));
}
__device__ __forceinline__ void mma16(float& c0, float& c1, float& c2, float& c3,
                                      uint32_t a0, uint32_t a1, uint32_t a2, uint32_t a3,
                                      uint32_t b0, uint32_t b1) {
    asm volatile("mma.sync.aligned.m16n8k16.row.col.f32.f16.f16.f32 "
                 "{%0,%1,%2,%3},{%4,%5,%6,%7},{%8,%9},{%0,%1,%2,%3};"
                 : "+f"(c0), "+f"(c1), "+f"(c2), "+f"(c3)
                 : "r"(a0), "r"(a1), "r"(a2), "r"(a3), "r"(b0), "r"(b1));
}
__device__ __forceinline__ uint32_t h2u(__half2 h) {
    return *reinterpret_cast<uint32_t*>(&h);
}
__device__ __forceinline__ void cp16(uint32_t dst, const void* src) {
    asm volatile("cp.async.ca.shared.global [%0], [%1], 16;"
                 :: "r"(dst), "l"(src) : "memory");
}

// --------------------------- weight quantize -------------------------------
__global__ __launch_bounds__(256) void wquant_kernel(
    const float* __restrict__ fe_w, const float* __restrict__ s_w,
    const float* __restrict__ e_w)
{
    const int m = blockIdx.x;   // 0..10
    const float* src = (m == 0) ? fe_w
                     : (m <= 2) ? s_w + (m - 1) * 4096
                                : e_w + (m - 3) * 4096;
    __half* dst = d_wq + m * 4096;
    for (int i = threadIdx.x; i < 4096; i += 256) dst[i] = __float2half_rn(src[i]);
}

// ------------------------------ Phase A ------------------------------------
// grid = 32 b * 128 tiles of 128 pix; block 256 = 8 warps.
__global__ void __launch_bounds__(256, 2) feat_kernel(
    const float* __restrict__ x, const float* __restrict__ fe_b)
{
    extern __shared__ __align__(16) char smem[];
    // [0, 16KB)  sxT [128 pix][64 c] half swz; reused as sc [128 pix][64 o]
    // [16KB, 24KB) swt [64 o][64 k] half swz
    const uint32_t smem_sh = (uint32_t)__cvta_generic_to_shared(smem);
    __shared__ float sb[64];
    __shared__ float red[8 * 64];

    const int tid = threadIdx.x, w = tid >> 5, l = tid & 31;
    const int b = blockIdx.x >> 7, pix0 = (blockIdx.x & 127) << 7;

    // x loads first (big latency), weights second, then convert/stage x
    float4 v[8];
    {
        const float* xb = x + (size_t)b * NPIX_B + pix0;
#pragma unroll
        for (int j = 0; j < 8; j++)
            v[j] = *(const float4*)(xb + (size_t)(8 * w + j) * NPIX + 4 * l);
    }
#pragma unroll
    for (int r = 0; r < 2; r++) {
        int i4 = tid + r * 256;
        uint4 wv = *(const uint4*)((const char*)d_wq + i4 * 16);
        *(uint4*)(smem + 16384 + swzb(i4 >> 3, i4 & 7)) = wv;
    }
    if (tid < 64) sb[tid] = fe_b[tid];
#pragma unroll
    for (int p = 0; p < 4; p++) {
        uint4 u;
        u.x = h2u(__floats2half2_rn(((float*)&v[0])[p], ((float*)&v[1])[p]));
        u.y = h2u(__floats2half2_rn(((float*)&v[2])[p], ((float*)&v[3])[p]));
        u.z = h2u(__floats2half2_rn(((float*)&v[4])[p], ((float*)&v[5])[p]));
        u.w = h2u(__floats2half2_rn(((float*)&v[6])[p], ((float*)&v[7])[p]));
        *(uint4*)(smem + swzb(4 * l + p, w)) = u;
    }
    __syncthreads();

    float acc[8][4];
    const int c0p = 2 * (l & 3);
#pragma unroll
    for (int nt = 0; nt < 8; nt++) {
        float b0v = sb[nt * 8 + c0p], b1v = sb[nt * 8 + c0p + 1];
        acc[nt][0] = b0v; acc[nt][1] = b1v;
        acc[nt][2] = b0v; acc[nt][3] = b1v;
    }

    const int tq = l >> 3, r8 = l & 7;
#pragma unroll
    for (int kk = 0; kk < 4; kk++) {
        const int aseg = 2 * kk + (tq >> 1);
        const int rsub = (tq & 1) * 8 + r8;
        uint32_t a0, a1, a2, a3;
        ldsm4(smem_sh + swzb(16 * w + rsub, aseg), a0, a1, a2, a3);
        uint32_t Bf[8][2];
#pragma unroll
        for (int g = 0; g < 4; g++) {
            uint32_t r0, r1, r2, r3;
            ldsm4(smem_sh + 16384 + swzb(16 * g + rsub, aseg), r0, r1, r2, r3);
            Bf[2 * g][0] = r0;     Bf[2 * g][1] = r2;
            Bf[2 * g + 1][0] = r1; Bf[2 * g + 1][1] = r3;
        }
#pragma unroll
        for (int nt = 0; nt < 8; nt++)
            mma16(acc[nt][0], acc[nt][1], acc[nt][2], acc[nt][3],
                  a0, a1, a2, a3, Bf[nt][0], Bf[nt][1]);
    }

#pragma unroll
    for (int nt = 0; nt < 8; nt++)
#pragma unroll
        for (int i = 0; i < 4; i++) acc[nt][i] = gelu_f(acc[nt][i]);

    // per-channel partial sums (fp32)
#pragma unroll
    for (int nt = 0; nt < 8; nt++) {
        float p0 = acc[nt][0] + acc[nt][2];
        float p1 = acc[nt][1] + acc[nt][3];
#pragma unroll
        for (int mk = 4; mk <= 16; mk <<= 1) {
            p0 += __shfl_xor_sync(0xffffffffu, p0, mk);
            p1 += __shfl_xor_sync(0xffffffffu, p1, mk);
        }
        if (l < 4) {
            red[w * 64 + nt * 8 + 2 * l]     = p0;
            red[w * 64 + nt * 8 + 2 * l + 1] = p1;
        }
    }

    __syncthreads();   // sxT/swt reads done -> reuse sxT region as sc
    {
        const int pr = 16 * w + (l >> 2);
#pragma unroll
        for (int nt = 0; nt < 8; nt++) {
            __half2 lo = __floats2half2_rn(acc[nt][0], acc[nt][1]);
            __half2 hi = __floats2half2_rn(acc[nt][2], acc[nt][3]);
            *(__half2*)(smem + swzb(pr, nt) + c0p * 2) = lo;
            *(__half2*)(smem + swzb(pr + 8, nt) + c0p * 2) = hi;
        }
    }
    __syncthreads();

    char* fb = (char*)(d_feat + ((size_t)b * NPIX + pix0) * 64);
#pragma unroll
    for (int r = 0; r < 4; r++) {
        int i4 = tid + r * 256;
        uint4 vv = *(uint4*)(smem + swzb(i4 >> 3, i4 & 7));
        *(uint4*)(fb + i4 * 16) = vv;
    }
    if (tid < 64) {
        float s = 0.f;
#pragma unroll
        for (int ww = 0; ww < 8; ww++) s += red[ww * 64 + tid];
        d_gf_part[tid * 4096 + blockIdx.x] = s;
    }
}

// ------------------------------ Phase C ------------------------------------
__global__ __launch_bounds__(256) void gate_kernel(
    const float* __restrict__ g1_w, const float* __restrict__ g1_b,
    const float* __restrict__ bn1_g, const float* __restrict__ bn1_b,
    const float* __restrict__ ca1_w, const float* __restrict__ ca1_b,
    const float* __restrict__ ca2_w, const float* __restrict__ ca2_b,
    const float* __restrict__ g2_w, const float* __restrict__ g2_b,
    const float* __restrict__ bn2_g, const float* __restrict__ bn2_b,
    const float* __restrict__ g3_w, const float* __restrict__ g3_b)
{
    __shared__ float sgf[32 * 64];
    __shared__ float sh1[32 * 128];
    __shared__ float sm[32 * 8];
    __shared__ float shh[32 * 64];
    __shared__ float ssc[32 * 8];
    const int tid = threadIdx.x;
    const float rs = rsqrtf(1.0f + 1e-5f);

    for (int i = tid; i < 2048; i += 256) {
        int bb = i >> 6, c = i & 63;
        const float4* pp = (const float4*)(d_gf_part + c * 4096 + bb * 128);
        float s = 0.f;
#pragma unroll 8
        for (int j = 0; j < 32; j++) {
            float4 v = pp[j];
            s += (v.x + v.y) + (v.z + v.w);
        }
        sgf[i] = s * (1.0f / 16384.0f);
    }
    __syncthreads();

    for (int i = tid; i < 32 * 128; i += 256) {
        int b = i >> 7, j = i & 127;
        float a = g1_b[j];
        const float* gr = sgf + b * 64;
        const float* wr = g1_w + j * 64;
#pragma unroll 8
        for (int c = 0; c < 64; c++) a = fmaf(gr[c], wr[c], a);
        a = a * (bn1_g[j] * rs) + bn1_b[j];
        sh1[i] = gelu_f(a);
    }
    __syncthreads();

    {
        int b = tid >> 3, k = tid & 7;
        float a = ca1_b[k];
        const float* hr = sh1 + b * 128;
        const float* wr = ca1_w + k * 128;
#pragma unroll 8
        for (int j = 0; j < 128; j++) a = fmaf(hr[j], wr[j], a);
        sm[tid] = gelu_f(a);
    }
    __syncthreads();

    for (int i = tid; i < 32 * 128; i += 256) {
        int b = i >> 7, j = i & 127;
        float a = ca2_b[j];
        const float* mr = sm + b * 8;
        const float* wr = ca2_w + j * 8;
#pragma unroll
        for (int k = 0; k < 8; k++) a = fmaf(mr[k], wr[k], a);
        sh1[i] *= 1.0f / (1.0f + expf(-2.0f * a));
    }
    __syncthreads();

    for (int i = tid; i < 32 * 64; i += 256) {
        int b = i >> 6, o = i & 63;
        float a = g2_b[o];
        const float* hr = sh1 + b * 128;
        const float* wr = g2_w + o * 128;
#pragma unroll 8
        for (int j = 0; j < 128; j++) a = fmaf(hr[j], wr[j], a);
        a = a * (bn2_g[o] * rs) + bn2_b[o];
        shh[i] = gelu_f(a);
    }
    __syncthreads();

    {
        int b = tid >> 3, e = tid & 7;
        float a = g3_b[e];
        const float* hr = shh + b * 64;
        const float* wr = g3_w + e * 64;
#pragma unroll 8
        for (int c = 0; c < 64; c++) a = fmaf(hr[c], wr[c], a);
        ssc[tid] = a;
    }
    __syncthreads();

    if (tid < 32) {
        const float* sc = ssc + tid * 8;
        int i1 = 0; float v1 = sc[0];
#pragma unroll
        for (int e = 1; e < 8; e++) if (sc[e] > v1) { v1 = sc[e]; i1 = e; }
        int i2 = -1; float v2 = -3.4e38f;
#pragma unroll
        for (int e = 0; e < 8; e++) if (e != i1 && sc[e] > v2) { v2 = sc[e]; i2 = e; }
        float w1 = 1.0f / (1.0f + expf((v2 - v1) * 0.5f));
        float* dw = d_dw + tid * 8;
#pragma unroll
        for (int e = 0; e < 8; e++) dw[e] = 0.0f;
        dw[i1] = w1;
        dw[i2] = 1.0f - w1;
    }
}

// ------------------------------ Phase D ------------------------------------
// grid = 32 b * 64 groups; each block sweeps 4 tiles of 64 pix.
// smem: [0,16K) sfB[2] double buffer; [16K,48K) weights x4; [48K,80K) combine.
__global__ void __launch_bounds__(256, 2) out_kernel(
    const float* __restrict__ s_b, const float* __restrict__ e_b,
    float* __restrict__ out)
{
    extern __shared__ __align__(16) char smem[];
    const uint32_t smem_sh = (uint32_t)__cvta_generic_to_shared(smem);
    __shared__ float Bv[256];
    __shared__ float cws[4];
    __shared__ int msel[4];

    const int tid = threadIdx.x, w = tid >> 5, l = tid & 31;
    const int b = blockIdx.x >> 6, grp = blockIdx.x & 63;

    if (tid == 0) {
        int s0 = -1, s1 = -1; float w0 = 0.f, w1 = 0.f;
        const float* dw = d_dw + b * 8;
#pragma unroll
        for (int e = 0; e < 8; e++) {
            float v = dw[e];
            if (v != 0.0f) { if (s0 < 0) { s0 = e; w0 = v; } else { s1 = e; w1 = v; } }
        }
        msel[0] = 1; msel[1] = 2; msel[2] = 3 + s0; msel[3] = 3 + s1;
        cws[0] = 0.5f; cws[1] = 0.5f; cws[2] = w0; cws[3] = w1;
    }

    // prefetch feature tiles 0 and 1 (independent of msel)
    const char* fbase = (const char*)(d_feat + ((size_t)b * NPIX + grp * 256) * 64);
#pragma unroll
    for (int t = 0; t < 2; t++) {
#pragma unroll
        for (int r = 0; r < 2; r++) {
            int i4 = tid + r * 256;
            cp16(smem_sh + t * 8192 + swzb(i4 >> 3, i4 & 7),
                 fbase + t * 8192 + i4 * 16);
        }
        asm volatile("cp.async.commit_group;" ::: "memory");
    }

    __syncthreads();   // msel visible

    // stage 4 weight matrices (resident for all tiles)
#pragma unroll
    for (int r = 0; r < 8; r++) {
        int idx = tid + r * 256;
        int m = idx >> 9, i4 = idx & 511;
        uint4 v = *(const uint4*)((const char*)d_wq + msel[m] * 8192 + i4 * 16);
        *(uint4*)(smem + 16384 + m * 8192 + swzb(i4 >> 3, i4 & 7)) = v;
    }
    if (tid < 64) {
        Bv[tid]       = s_b[tid];
        Bv[64 + tid]  = s_b[64 + tid];
        Bv[128 + tid] = e_b[(msel[2] - 3) * 64 + tid];
        Bv[192 + tid] = e_b[(msel[3] - 3) * 64 + tid];
    }
    __syncthreads();   // weights + Bv visible

    const int q = w & 3, g = w >> 2;
    const int ma = 2 * g, mb = 2 * g + 1;
    const uint32_t swa = smem_sh + 16384 + ma * 8192;
    const uint32_t swb = smem_sh + 16384 + mb * 8192;
    const int ro = 16 * q + (l >> 2), c0p = 2 * (l & 3);
    const int tq = l >> 3, r8 = l & 7;

    const float bA0 = Bv[ma * 64 + ro], bA1 = Bv[ma * 64 + ro + 8];
    const float bB0 = Bv[mb * 64 + ro], bB1 = Bv[mb * 64 + ro + 8];
    const float ca = cws[ma], cb = cws[mb];
    float* comb = (float*)(smem + 49152);
    float* myb = comb + g * 4096;

#pragma unroll 1
    for (int t = 0; t < 4; t++) {
        asm volatile("cp.async.wait_group 1;" ::: "memory");
        __syncthreads();   // tile t visible; prev tile's comb reads done

        const uint32_t sfb = smem_sh + (t & 1) * 8192;
        float accA[8][4], accB[8][4];
#pragma unroll
        for (int nt = 0; nt < 8; nt++) {
            accA[nt][0] = bA0; accA[nt][1] = bA0; accA[nt][2] = bA1; accA[nt][3] = bA1;
            accB[nt][0] = bB0; accB[nt][1] = bB0; accB[nt][2] = bB1; accB[nt][3] = bB1;
        }

#pragma unroll
        for (int kk = 0; kk < 4; kk++) {
            const int aseg = 2 * kk + (tq >> 1);
            const int rsub = (tq & 1) * 8 + r8;
            uint32_t Bf[8][2];
#pragma unroll
            for (int g2 = 0; g2 < 4; g2++) {
                uint32_t r0, r1, r2, r3;
                ldsm4(sfb + swzb(16 * g2 + rsub, aseg), r0, r1, r2, r3);
                Bf[2 * g2][0] = r0;     Bf[2 * g2][1] = r2;
                Bf[2 * g2 + 1][0] = r1; Bf[2 * g2 + 1][1] = r3;
            }
            uint32_t a0, a1, a2, a3;
            ldsm4(swa + swzb(16 * q + rsub, aseg), a0, a1, a2, a3);
#pragma unroll
            for (int nt = 0; nt < 8; nt++)
                mma16(accA[nt][0], accA[nt][1], accA[nt][2], accA[nt][3],
                      a0, a1, a2, a3, Bf[nt][0], Bf[nt][1]);
            ldsm4(swb + swzb(16 * q + rsub, aseg), a0, a1, a2, a3);
#pragma unroll
            for (int nt = 0; nt < 8; nt++)
                mma16(accB[nt][0], accB[nt][1], accB[nt][2], accB[nt][3],
                      a0, a1, a2, a3, Bf[nt][0], Bf[nt][1]);
        }
        __syncthreads();   // all warps done reading sfB[t&1]

        if (t + 2 < 4) {
            const char* fsrc = fbase + (t + 2) * 8192;
#pragma unroll
            for (int r = 0; r < 2; r++) {
                int i4 = tid + r * 256;
                cp16(smem_sh + (t & 1) * 8192 + swzb(i4 >> 3, i4 & 7),
                     fsrc + i4 * 16);
            }
        }
        asm volatile("cp.async.commit_group;" ::: "memory");

        // epilogue: gelu + coef combine (2 mats in regs), stage to comb
#pragma unroll
        for (int nt = 0; nt < 8; nt++) {
            int pix = nt * 8 + c0p;
            float v0 = ca * gelu_f(accA[nt][0]) + cb * gelu_f(accB[nt][0]);
            float v1 = ca * gelu_f(accA[nt][1]) + cb * gelu_f(accB[nt][1]);
            float v2 = ca * gelu_f(accA[nt][2]) + cb * gelu_f(accB[nt][2]);
            float v3 = ca * gelu_f(accA[nt][3]) + cb * gelu_f(accB[nt][3]);
            *(float2*)(myb + swz(ro, pix >> 2) + (pix & 3))     = make_float2(v0, v1);
            *(float2*)(myb + swz(ro + 8, pix >> 2) + (pix & 3)) = make_float2(v2, v3);
        }
        __syncthreads();

        float* ob = out + (size_t)b * NPIX_B + grp * 256 + t * 64;
#pragma unroll
        for (int r = 0; r < 4; r++) {
            int i4 = tid + r * 256;
            int o = i4 >> 4, seg = i4 & 15;
            int off = swz(o, seg);
            float4 va = *(const float4*)(comb + off);
            float4 vb = *(const float4*)(comb + 4096 + off);
            float4 rr;
            rr.x = va.x + vb.x; rr.y = va.y + vb.y;
            rr.z = va.z + vb.z; rr.w = va.w + vb.w;
            *(float4*)(ob + (size_t)o * NPIX + seg * 4) = rr;
        }
    }
}

// ---------------------------------------------------------------------------
extern "C" void kernel_launch(void* const* d_in, const int* in_sizes, int n_in,
                              void* d_out, int out_size)
{
    const float* x     = (const float*)d_in[0];
    const float* fe_w  = (const float*)d_in[1];
    const float* fe_b  = (const float*)d_in[2];
    const float* s_w   = (const float*)d_in[3];
    const float* s_b   = (const float*)d_in[4];
    const float* e_w   = (const float*)d_in[5];
    const float* e_b   = (const float*)d_in[6];
    const float* g1_w  = (const float*)d_in[7];
    const float* g1_b  = (const float*)d_in[8];
    const float* bn1_g = (const float*)d_in[9];
    const float* bn1_b = (const float*)d_in[10];
    const float* ca1_w = (const float*)d_in[11];
    const float* ca1_b = (const float*)d_in[12];
    const float* ca2_w = (const float*)d_in[13];
    const float* ca2_b = (const float*)d_in[14];
    const float* g2_w  = (const float*)d_in[15];
    const float* g2_b  = (const float*)d_in[16];
    const float* bn2_g = (const float*)d_in[17];
    const float* bn2_b = (const float*)d_in[18];
    const float* g3_w  = (const float*)d_in[19];
    const float* g3_b  = (const float*)d_in[20];
    float* out = (float*)d_out;

    static bool attr_done = false;
    if (!attr_done) {
        cudaFuncSetAttribute(out_kernel,
                             cudaFuncAttributeMaxDynamicSharedMemorySize, 81920);
        attr_done = true;
    }

    wquant_kernel<<<11, 256>>>(fe_w, s_w, e_w);
    feat_kernel<<<4096, 256, 24576>>>(x, fe_b);
    gate_kernel<<<1, 256>>>(g1_w, g1_b, bn1_g, bn1_b, ca1_w, ca1_b,
                            ca2_w, ca2_b, g2_w, g2_b, bn2_g, bn2_b,
                            g3_w, g3_b);
    out_kernel<<<2048, 256, 81920>>>(s_b, e_b, out);
}

// round 17
// speedup vs baseline: 1.1318x; 1.0535x over previous
#include <cuda_runtime.h>
#include <cuda_fp16.h>
#include <math.h>
#include <stdint.h>

// ---------------------------------------------------------------------------
// MoEImage via fp16 mma.sync m16n8k16 (fp32 accumulate).
//   wquant : round 11 64x64 weight matrices to fp16 ([o][k] layout)
//   feat   : persistent 4-tile blocks, cp.async double-buffered x tiles,
//            smem transpose+convert, F = gelu(x@W^T+b) -> d_feat [b][pix][c]
//   gate   : reduce gf partials -> MLP -> top2 -> d_dw
//   out    : persistent 4-tile blocks, resident weights, cp.async features
// ---------------------------------------------------------------------------

#define NPIX   16384
#define NPIX_B (64 * 16384)

__device__ __align__(16) __half d_feat[32 * 64 * 16384];   // [b][pix][c], 64 MiB
__device__ float d_gf_part[64 * 1024];                     // [c][block]
__device__ float d_dw[32 * 8];
__device__ __align__(16) __half d_wq[11 * 4096];           // 0: fe, 1-2: shared, 3-10: experts

// Branchless erf-based gelu (A&S 7.1.26, abs err ~1.5e-7) using MUFU rcp/ex2.
__device__ __forceinline__ float gelu_f(float v) {
    float u = fabsf(v) * 0.70710678118654752440f;
    float d;
    asm("rcp.approx.f32 %0, %1;" : "=f"(d) : "f"(fmaf(0.3275911f, u, 1.0f)));
    float p = fmaf(d, 1.061405429f, -1.453152027f);
    p = fmaf(d, p, 1.421413741f);
    p = fmaf(d, p, -0.284496736f);
    p = fmaf(d, p, 0.254829592f);
    p = p * d;
    float e;
    asm("ex2.approx.f32 %0, %1;" : "=f"(e)
        : "f"(u * u * -1.4426950408889634f));
    float erfu = fmaf(-p, e, 1.0f);          // erf(u), u >= 0
    float s = copysignf(erfu, v);
    float hv = 0.5f * v;
    return fmaf(hv, s, hv);
}
// half tiles: rows of 64 halves = 128B = 8 segs of 16B; byte offset
__device__ __forceinline__ int swzb(int row, int seg) {
    return row * 128 + ((seg ^ ((row ^ (row >> 3)) & 7)) << 4);
}
// f32 tiles: rows of 64 floats = 16 segs of 16B; float offset
__device__ __forceinline__ int swz(int row, int seg) {
    return (row << 6) + ((seg ^ ((row ^ (row >> 3)) & 7)) << 2);
}
__device__ __forceinline__ void ldsm4(uint32_t a, uint32_t& r0, uint32_t& r1,
                                      uint32_t& r2, uint32_t& r3) {
    asm volatile("ldmatrix.sync.aligned.m8n8.x4.shared.b16 {%0,%1,%2,%3}, [%4];"
                 : "=r"(r0), "=r"(r1), "=r"(r2), "=r"(r3) : "r"(a));
}
__device__ __forceinline__ void mma16(float& c0, float& c1, float& c2, float& c3,
                                      uint32_t a0, uint32_t a1, uint32_t a2, uint32_t a3,
                                      uint32_t b0, uint32_t b1) {
    asm volatile("mma.sync.aligned.m16n8k16.row.col.f32.f16.f16.f32 "
                 "{%0,%1,%2,%3},{%4,%5,%6,%7},{%8,%9},{%0,%1,%2,%3};"
                 : "+f"(c0), "+f"(c1), "+f"(c2), "+f"(c3)
                 : "r"(a0), "r"(a1), "r"(a2), "r"(a3), "r"(b0), "r"(b1));
}
__device__ __forceinline__ uint32_t h2u(__half2 h) {
    return *reinterpret_cast<uint32_t*>(&h);
}
__device__ __forceinline__ void cp16(uint32_t dst, const void* src) {
    asm volatile("cp.async.ca.shared.global [%0], [%1], 16;"
                 :: "r"(dst), "l"(src) : "memory");
}

// --------------------------- weight quantize -------------------------------
__global__ __launch_bounds__(256) void wquant_kernel(
    const float* __restrict__ fe_w, const float* __restrict__ s_w,
    const float* __restrict__ e_w)
{
    const int m = blockIdx.x;   // 0..10
    const float* src = (m == 0) ? fe_w
                     : (m <= 2) ? s_w + (m - 1) * 4096
                                : e_w + (m - 3) * 4096;
    __half* dst = d_wq + m * 4096;
    for (int i = threadIdx.x; i < 4096; i += 256) dst[i] = __float2half_rn(src[i]);
}

// ------------------------------ Phase A ------------------------------------
// grid = 32 b * 32 groups; each block sweeps 4 tiles of 128 pix.
// smem: [0,64K) xbuf[2] f32 [64c][128pix]; [64K,80K) sxT half swz (reused sc);
//       [80K,88K) swt half swz.
__global__ void __launch_bounds__(256, 2) feat_kernel(
    const float* __restrict__ x, const float* __restrict__ fe_b)
{
    extern __shared__ __align__(16) char smem[];
    const uint32_t smem_sh = (uint32_t)__cvta_generic_to_shared(smem);
    const uint32_t sxT_sh = smem_sh + 65536;
    const uint32_t swt_sh = smem_sh + 81920;
    char* sxT = smem + 65536;
    char* swt = smem + 81920;
    __shared__ float sb[64];
    __shared__ float red[512];

    const int tid = threadIdx.x, w = tid >> 5, l = tid & 31;
    const int b = blockIdx.x >> 5, grp = blockIdx.x & 31;
    const float* xb = x + (size_t)b * NPIX_B + grp * 512;

    // prefetch x tiles 0,1 (raw f32, [c][128 pix], no swizzle needed)
#pragma unroll
    for (int t = 0; t < 2; t++) {
#pragma unroll
        for (int r = 0; r < 8; r++) {
            int idx = tid + r * 256;          // 0..2047
            int row = idx >> 5, ch = idx & 31;
            cp16(smem_sh + t * 32768 + row * 512 + ch * 16,
                 xb + t * 128 + (size_t)row * NPIX + ch * 4);
        }
        asm volatile("cp.async.commit_group;" ::: "memory");
    }

    // stage fe weights (resident for all 4 tiles)
#pragma unroll
    for (int r = 0; r < 2; r++) {
        int i4 = tid + r * 256;
        uint4 wv = *(const uint4*)((const char*)d_wq + i4 * 16);
        *(uint4*)(swt + swzb(i4 >> 3, i4 & 7)) = wv;
    }
    if (tid < 64) sb[tid] = fe_b[tid];
    red[tid] = 0.0f; red[tid + 256] = 0.0f;

    const int c0p = 2 * (l & 3);
    const int tq = l >> 3, r8v = l & 7;

#pragma unroll 1
    for (int t = 0; t < 4; t++) {
        asm volatile("cp.async.wait_group 1;" ::: "memory");
        __syncthreads();   // xbuf[t&1] ready; prev tile's sc reads done

        // transpose+convert from smem: warp w owns channels 8w..8w+7
        {
            const float* xs = (const float*)(smem + (t & 1) * 32768);
            float4 v[8];
#pragma unroll
            for (int j = 0; j < 8; j++)
                v[j] = *(const float4*)(xs + (8 * w + j) * 128 + 4 * l);
#pragma unroll
            for (int p = 0; p < 4; p++) {
                uint4 u;
                u.x = h2u(__floats2half2_rn(((float*)&v[0])[p], ((float*)&v[1])[p]));
                u.y = h2u(__floats2half2_rn(((float*)&v[2])[p], ((float*)&v[3])[p]));
                u.z = h2u(__floats2half2_rn(((float*)&v[4])[p], ((float*)&v[5])[p]));
                u.w = h2u(__floats2half2_rn(((float*)&v[6])[p], ((float*)&v[7])[p]));
                *(uint4*)(sxT + swzb(4 * l + p, w)) = u;
            }
        }
        __syncthreads();   // sxT + (first iter) swt/sb visible; xbuf consumed

        // prefetch x tile t+2 into the buffer just freed
        if (t < 2) {
#pragma unroll
            for (int r = 0; r < 8; r++) {
                int idx = tid + r * 256;
                int row = idx >> 5, ch = idx & 31;
                cp16(smem_sh + (t & 1) * 32768 + row * 512 + ch * 16,
                     xb + (t + 2) * 128 + (size_t)row * NPIX + ch * 4);
            }
        }
        asm volatile("cp.async.commit_group;" ::: "memory");

        float acc[8][4];
#pragma unroll
        for (int nt = 0; nt < 8; nt++) {
            float b0v = sb[nt * 8 + c0p], b1v = sb[nt * 8 + c0p + 1];
            acc[nt][0] = b0v; acc[nt][1] = b1v;
            acc[nt][2] = b0v; acc[nt][3] = b1v;
        }

#pragma unroll
        for (int kk = 0; kk < 4; kk++) {
            const int aseg = 2 * kk + (tq >> 1);
            const int rsub = (tq & 1) * 8 + r8v;
            uint32_t a0, a1, a2, a3;
            ldsm4(sxT_sh + swzb(16 * w + rsub, aseg), a0, a1, a2, a3);
            uint32_t Bf[8][2];
#pragma unroll
            for (int g = 0; g < 4; g++) {
                uint32_t r0, r1, r2, r3;
                ldsm4(swt_sh + swzb(16 * g + rsub, aseg), r0, r1, r2, r3);
                Bf[2 * g][0] = r0;     Bf[2 * g][1] = r2;
                Bf[2 * g + 1][0] = r1; Bf[2 * g + 1][1] = r3;
            }
#pragma unroll
            for (int nt = 0; nt < 8; nt++)
                mma16(acc[nt][0], acc[nt][1], acc[nt][2], acc[nt][3],
                      a0, a1, a2, a3, Bf[nt][0], Bf[nt][1]);
        }

#pragma unroll
        for (int nt = 0; nt < 8; nt++)
#pragma unroll
            for (int i = 0; i < 4; i++) acc[nt][i] = gelu_f(acc[nt][i]);

        // per-channel partial sums, accumulated across tiles in red[]
#pragma unroll
        for (int nt = 0; nt < 8; nt++) {
            float p0 = acc[nt][0] + acc[nt][2];
            float p1 = acc[nt][1] + acc[nt][3];
#pragma unroll
            for (int mk = 4; mk <= 16; mk <<= 1) {
                p0 += __shfl_xor_sync(0xffffffffu, p0, mk);
                p1 += __shfl_xor_sync(0xffffffffu, p1, mk);
            }
            if (l < 4) {
                red[w * 64 + nt * 8 + 2 * l]     += p0;
                red[w * 64 + nt * 8 + 2 * l + 1] += p1;
            }
        }

        __syncthreads();   // all warps done reading sxT -> reuse as sc
        {
            const int pr = 16 * w + (l >> 2);
#pragma unroll
            for (int nt = 0; nt < 8; nt++) {
                __half2 lo = __floats2half2_rn(acc[nt][0], acc[nt][1]);
                __half2 hi = __floats2half2_rn(acc[nt][2], acc[nt][3]);
                *(__half2*)(sxT + swzb(pr, nt) + c0p * 2) = lo;
                *(__half2*)(sxT + swzb(pr + 8, nt) + c0p * 2) = hi;
            }
        }
        __syncthreads();

        char* fbp = (char*)(d_feat + ((size_t)b * NPIX + grp * 512 + t * 128) * 64);
#pragma unroll
        for (int r = 0; r < 4; r++) {
            int i4 = tid + r * 256;
            uint4 vv = *(uint4*)(sxT + swzb(i4 >> 3, i4 & 7));
            *(uint4*)(fbp + i4 * 16) = vv;
        }
    }

    if (tid < 64) {
        float s = 0.f;
#pragma unroll
        for (int ww = 0; ww < 8; ww++) s += red[ww * 64 + tid];
        d_gf_part[tid * 1024 + blockIdx.x] = s;
    }
}

// ------------------------------ Phase C ------------------------------------
__global__ __launch_bounds__(256) void gate_kernel(
    const float* __restrict__ g1_w, const float* __restrict__ g1_b,
    const float* __restrict__ bn1_g, const float* __restrict__ bn1_b,
    const float* __restrict__ ca1_w, const float* __restrict__ ca1_b,
    const float* __restrict__ ca2_w, const float* __restrict__ ca2_b,
    const float* __restrict__ g2_w, const float* __restrict__ g2_b,
    const float* __restrict__ bn2_g, const float* __restrict__ bn2_b,
    const float* __restrict__ g3_w, const float* __restrict__ g3_b)
{
    __shared__ float sgf[32 * 64];
    __shared__ float sh1[32 * 128];
    __shared__ float sm[32 * 8];
    __shared__ float shh[32 * 64];
    __shared__ float ssc[32 * 8];
    const int tid = threadIdx.x;
    const float rs = rsqrtf(1.0f + 1e-5f);

    for (int i = tid; i < 2048; i += 256) {
        int bb = i >> 6, c = i & 63;
        const float4* pp = (const float4*)(d_gf_part + c * 1024 + bb * 32);
        float s = 0.f;
#pragma unroll
        for (int j = 0; j < 8; j++) {
            float4 v = pp[j];
            s += (v.x + v.y) + (v.z + v.w);
        }
        sgf[i] = s * (1.0f / 16384.0f);
    }
    __syncthreads();

    for (int i = tid; i < 32 * 128; i += 256) {
        int b = i >> 7, j = i & 127;
        float a = g1_b[j];
        const float* gr = sgf + b * 64;
        const float* wr = g1_w + j * 64;
#pragma unroll 8
        for (int c = 0; c < 64; c++) a = fmaf(gr[c], wr[c], a);
        a = a * (bn1_g[j] * rs) + bn1_b[j];
        sh1[i] = gelu_f(a);
    }
    __syncthreads();

    {
        int b = tid >> 3, k = tid & 7;
        float a = ca1_b[k];
        const float* hr = sh1 + b * 128;
        const float* wr = ca1_w + k * 128;
#pragma unroll 8
        for (int j = 0; j < 128; j++) a = fmaf(hr[j], wr[j], a);
        sm[tid] = gelu_f(a);
    }
    __syncthreads();

    for (int i = tid; i < 32 * 128; i += 256) {
        int b = i >> 7, j = i & 127;
        float a = ca2_b[j];
        const float* mr = sm + b * 8;
        const float* wr = ca2_w + j * 8;
#pragma unroll
        for (int k = 0; k < 8; k++) a = fmaf(mr[k], wr[k], a);
        sh1[i] *= 1.0f / (1.0f + expf(-2.0f * a));
    }
    __syncthreads();

    for (int i = tid; i < 32 * 64; i += 256) {
        int b = i >> 6, o = i & 63;
        float a = g2_b[o];
        const float* hr = sh1 + b * 128;
        const float* wr = g2_w + o * 128;
#pragma unroll 8
        for (int j = 0; j < 128; j++) a = fmaf(hr[j], wr[j], a);
        a = a * (bn2_g[o] * rs) + bn2_b[o];
        shh[i] = gelu_f(a);
    }
    __syncthreads();

    {
        int b = tid >> 3, e = tid & 7;
        float a = g3_b[e];
        const float* hr = shh + b * 64;
        const float* wr = g3_w + e * 64;
#pragma unroll 8
        for (int c = 0; c < 64; c++) a = fmaf(hr[c], wr[c], a);
        ssc[tid] = a;
    }
    __syncthreads();

    if (tid < 32) {
        const float* sc = ssc + tid * 8;
        int i1 = 0; float v1 = sc[0];
#pragma unroll
        for (int e = 1; e < 8; e++) if (sc[e] > v1) { v1 = sc[e]; i1 = e; }
        int i2 = -1; float v2 = -3.4e38f;
#pragma unroll
        for (int e = 0; e < 8; e++) if (e != i1 && sc[e] > v2) { v2 = sc[e]; i2 = e; }
        float w1 = 1.0f / (1.0f + expf((v2 - v1) * 0.5f));
        float* dw = d_dw + tid * 8;
#pragma unroll
        for (int e = 0; e < 8; e++) dw[e] = 0.0f;
        dw[i1] = w1;
        dw[i2] = 1.0f - w1;
    }
}

// ------------------------------ Phase D ------------------------------------
// grid = 32 b * 64 groups; each block sweeps 4 tiles of 64 pix.
// smem: [0,16K) sfB[2] double buffer; [16K,48K) weights x4; [48K,80K) combine.
__global__ void __launch_bounds__(256, 2) out_kernel(
    const float* __restrict__ s_b, const float* __restrict__ e_b,
    float* __restrict__ out)
{
    extern __shared__ __align__(16) char smem[];
    const uint32_t smem_sh = (uint32_t)__cvta_generic_to_shared(smem);
    __shared__ float Bv[256];
    __shared__ float cws[4];
    __shared__ int msel[4];

    const int tid = threadIdx.x, w = tid >> 5, l = tid & 31;
    const int b = blockIdx.x >> 6, grp = blockIdx.x & 63;

    if (tid == 0) {
        int s0 = -1, s1 = -1; float w0 = 0.f, w1 = 0.f;
        const float* dw = d_dw + b * 8;
#pragma unroll
        for (int e = 0; e < 8; e++) {
            float v = dw[e];
            if (v != 0.0f) { if (s0 < 0) { s0 = e; w0 = v; } else { s1 = e; w1 = v; } }
        }
        msel[0] = 1; msel[1] = 2; msel[2] = 3 + s0; msel[3] = 3 + s1;
        cws[0] = 0.5f; cws[1] = 0.5f; cws[2] = w0; cws[3] = w1;
    }

    const char* fbase = (const char*)(d_feat + ((size_t)b * NPIX + grp * 256) * 64);
#pragma unroll
    for (int t = 0; t < 2; t++) {
#pragma unroll
        for (int r = 0; r < 2; r++) {
            int i4 = tid + r * 256;
            cp16(smem_sh + t * 8192 + swzb(i4 >> 3, i4 & 7),
                 fbase + t * 8192 + i4 * 16);
        }
        asm volatile("cp.async.commit_group;" ::: "memory");
    }

    __syncthreads();   // msel visible

#pragma unroll
    for (int r = 0; r < 8; r++) {
        int idx = tid + r * 256;
        int m = idx >> 9, i4 = idx & 511;
        uint4 v = *(const uint4*)((const char*)d_wq + msel[m] * 8192 + i4 * 16);
        *(uint4*)(smem + 16384 + m * 8192 + swzb(i4 >> 3, i4 & 7)) = v;
    }
    if (tid < 64) {
        Bv[tid]       = s_b[tid];
        Bv[64 + tid]  = s_b[64 + tid];
        Bv[128 + tid] = e_b[(msel[2] - 3) * 64 + tid];
        Bv[192 + tid] = e_b[(msel[3] - 3) * 64 + tid];
    }
    __syncthreads();   // weights + Bv visible

    const int q = w & 3, g = w >> 2;
    const int ma = 2 * g, mb = 2 * g + 1;
    const uint32_t swa = smem_sh + 16384 + ma * 8192;
    const uint32_t swb = smem_sh + 16384 + mb * 8192;
    const int ro = 16 * q + (l >> 2), c0p = 2 * (l & 3);
    const int tq = l >> 3, r8 = l & 7;

    const float bA0 = Bv[ma * 64 + ro], bA1 = Bv[ma * 64 + ro + 8];
    const float bB0 = Bv[mb * 64 + ro], bB1 = Bv[mb * 64 + ro + 8];
    const float ca = cws[ma], cb = cws[mb];
    float* comb = (float*)(smem + 49152);
    float* myb = comb + g * 4096;

#pragma unroll 1
    for (int t = 0; t < 4; t++) {
        asm volatile("cp.async.wait_group 1;" ::: "memory");
        __syncthreads();

        const uint32_t sfb = smem_sh + (t & 1) * 8192;
        float accA[8][4], accB[8][4];
#pragma unroll
        for (int nt = 0; nt < 8; nt++) {
            accA[nt][0] = bA0; accA[nt][1] = bA0; accA[nt][2] = bA1; accA[nt][3] = bA1;
            accB[nt][0] = bB0; accB[nt][1] = bB0; accB[nt][2] = bB1; accB[nt][3] = bB1;
        }

#pragma unroll
        for (int kk = 0; kk < 4; kk++) {
            const int aseg = 2 * kk + (tq >> 1);
            const int rsub = (tq & 1) * 8 + r8;
            uint32_t Bf[8][2];
#pragma unroll
            for (int g2 = 0; g2 < 4; g2++) {
                uint32_t r0, r1, r2, r3;
                ldsm4(sfb + swzb(16 * g2 + rsub, aseg), r0, r1, r2, r3);
                Bf[2 * g2][0] = r0;     Bf[2 * g2][1] = r2;
                Bf[2 * g2 + 1][0] = r1; Bf[2 * g2 + 1][1] = r3;
            }
            uint32_t a0, a1, a2, a3;
            ldsm4(swa + swzb(16 * q + rsub, aseg), a0, a1, a2, a3);
#pragma unroll
            for (int nt = 0; nt < 8; nt++)
                mma16(accA[nt][0], accA[nt][1], accA[nt][2], accA[nt][3],
                      a0, a1, a2, a3, Bf[nt][0], Bf[nt][1]);
            ldsm4(swb + swzb(16 * q + rsub, aseg), a0, a1, a2, a3);
#pragma unroll
            for (int nt = 0; nt < 8; nt++)
                mma16(accB[nt][0], accB[nt][1], accB[nt][2], accB[nt][3],
                      a0, a1, a2, a3, Bf[nt][0], Bf[nt][1]);
        }
        __syncthreads();

        if (t + 2 < 4) {
            const char* fsrc = fbase + (t + 2) * 8192;
#pragma unroll
            for (int r = 0; r < 2; r++) {
                int i4 = tid + r * 256;
                cp16(smem_sh + (t & 1) * 8192 + swzb(i4 >> 3, i4 & 7),
                     fsrc + i4 * 16);
            }
        }
        asm volatile("cp.async.commit_group;" ::: "memory");

#pragma unroll
        for (int nt = 0; nt < 8; nt++) {
            int pix = nt * 8 + c0p;
            float v0 = ca * gelu_f(accA[nt][0]) + cb * gelu_f(accB[nt][0]);
            float v1 = ca * gelu_f(accA[nt][1]) + cb * gelu_f(accB[nt][1]);
            float v2 = ca * gelu_f(accA[nt][2]) + cb * gelu_f(accB[nt][2]);
            float v3 = ca * gelu_f(accA[nt][3]) + cb * gelu_f(accB[nt][3]);
            *(float2*)(myb + swz(ro, pix >> 2) + (pix & 3))     = make_float2(v0, v1);
            *(float2*)(myb + swz(ro + 8, pix >> 2) + (pix & 3)) = make_float2(v2, v3);
        }
        __syncthreads();

        float* ob = out + (size_t)b * NPIX_B + grp * 256 + t * 64;
#pragma unroll
        for (int r = 0; r < 4; r++) {
            int i4 = tid + r * 256;
            int o = i4 >> 4, seg = i4 & 15;
            int off = swz(o, seg);
            float4 va = *(const float4*)(comb + off);
            float4 vb = *(const float4*)(comb + 4096 + off);
            float4 rr;
            rr.x = va.x + vb.x; rr.y = va.y + vb.y;
            rr.z = va.z + vb.z; rr.w = va.w + vb.w;
            *(float4*)(ob + (size_t)o * NPIX + seg * 4) = rr;
        }
    }
}

// ---------------------------------------------------------------------------
extern "C" void kernel_launch(void* const* d_in, const int* in_sizes, int n_in,
                              void* d_out, int out_size)
{
    const float* x     = (const float*)d_in[0];
    const float* fe_w  = (const float*)d_in[1];
    const float* fe_b  = (const float*)d_in[2];
    const float* s_w   = (const float*)d_in[3];
    const float* s_b   = (const float*)d_in[4];
    const float* e_w   = (const float*)d_in[5];
    const float* e_b   = (const float*)d_in[6];
    const float* g1_w  = (const float*)d_in[7];
    const float* g1_b  = (const float*)d_in[8];
    const float* bn1_g = (const float*)d_in[9];
    const float* bn1_b = (const float*)d_in[10];
    const float* ca1_w = (const float*)d_in[11];
    const float* ca1_b = (const float*)d_in[12];
    const float* ca2_w = (const float*)d_in[13];
    const float* ca2_b = (const float*)d_in[14];
    const float* g2_w  = (const float*)d_in[15];
    const float* g2_b  = (const float*)d_in[16];
    const float* bn2_g = (const float*)d_in[17];
    const float* bn2_b = (const float*)d_in[18];
    const float* g3_w  = (const float*)d_in[19];
    const float* g3_b  = (const float*)d_in[20];
    float* out = (float*)d_out;

    static bool attr_done = false;
    if (!attr_done) {
        cudaFuncSetAttribute(feat_kernel,
                             cudaFuncAttributeMaxDynamicSharedMemorySize, 90112);
        cudaFuncSetAttribute(out_kernel,
                             cudaFuncAttributeMaxDynamicSharedMemorySize, 81920);
        attr_done = true;
    }

    wquant_kernel<<<11, 256>>>(fe_w, s_w, e_w);
    feat_kernel<<<1024, 256, 90112>>>(x, fe_b);
    gate_kernel<<<1, 256>>>(g1_w, g1_b, bn1_g, bn1_b, ca1_w, ca1_b,
                            ca2_w, ca2_b, g2_w, g2_b, bn2_g, bn2_b,
                            g3_w, g3_b);
    out_kernel<<<2048, 256, 81920>>>(s_b, e_b, out);
}